// round 7
// baseline (speedup 1.0000x reference)
#include <cuda_runtime.h>
#include <math.h>

#define BB 16
#define CIN 20
#define HH 256
#define WW 256
#define WID 64
#define M1V 16
#define M2V 16
#define NLAY 4
#define FCH 128
#define CO 20
#define HW 65536
#define NPIX (BB*HW)

#define TWO_PI 6.28318530717958647692f

typedef unsigned long long ull;

// ---------------- scratch (device globals; no allocations allowed) ----------------
__device__ float  g_h0[(size_t)BB*WID*HW];            // 268 MB ping
__device__ float  g_h1[(size_t)BB*WID*HW];            // 268 MB pong
__device__ float2 g_Fw[(size_t)BB*WID*HH*M2V];        // (b,c,h,ky)  33.5 MB
__device__ float2 g_Fm[(size_t)BB*WID*32*M2V];        // (b,c,kxi,ky) 4 MB
__device__ float2 g_Gm[(size_t)BB*WID*32*M2V];        // 4 MB
__device__ float2 g_Gw[(size_t)BB*WID*HH*M2V];        // (b,c,h,ky)  33.5 MB
__device__ float2 g_Wt[(size_t)NLAY*512*WID*WID];     // (l,m,i,o)   67 MB
__device__ ull    g_pwdup[NLAY*WID*WID];              // (l,i,o) dup pairs, 131 KB
__device__ float2 g_Tfw[M2V*WW];                      // e^{-2pi i ky w/256}, [ky*256+w]
__device__ ull    g_TfwT[WW*M2V];                     // same, transposed [w*16+ky]
__device__ ull    g_Tsyn[WW*M2V];                     // e^{+2pi i ky w/256}, [w*16+ky]
__device__ float2 g_Tfh[32*HH];                       // e^{-2pi i kx h/256}, kx in R
__device__ float2 g_Tih[32*HH];                       // conj of above

// ---- packed f32x2 helpers ----
__device__ __forceinline__ ull ff2(ull a, ull b, ull c) {
    ull d; asm("fma.rn.f32x2 %0,%1,%2,%3;" : "=l"(d) : "l"(a), "l"(b), "l"(c)); return d;
}
__device__ __forceinline__ ull pk(float x, float y) {
    ull d; asm("mov.b64 %0,{%1,%2};" : "=l"(d) : "f"(x), "f"(y)); return d;
}
__device__ __forceinline__ float2 upk(ull u) {
    float2 f; asm("mov.b64 {%0,%1},%2;" : "=f"(f.x), "=f"(f.y) : "l"(u)); return f;
}

// ---- fast erf-based gelu (Abramowitz-Stegun 7.1.26, |eps|<=1.5e-7) ----
__device__ __forceinline__ float gelu_fast(float v) {
    float z  = 0.70710678118654752440f * v;
    float az = fabsf(z);
    float t  = __fdividef(1.0f, fmaf(0.3275911f, az, 1.0f));
    float e  = __expf(-az * az);
    float p  = t * (0.254829592f + t * (-0.284496736f + t * (1.421413741f +
               t * (-1.453152027f + t * 1.061405429f))));
    float er = fmaf(-p, e, 1.0f);
    er = copysignf(er, z);
    return 0.5f * v * (1.0f + er);
}

// ---------------- twiddle init ----------------
__global__ void k_twiddle() {
    int idx = blockIdx.x * blockDim.x + threadIdx.x;   // 8192 threads
    if (idx < M2V * WW) {
        int ky = idx >> 8, w = idx & 255;
        int ph = (ky * w) & 255;                       // exact phase mod 256
        float s, c;
        sincosf(-TWO_PI * (float)ph * (1.0f / 256.0f), &s, &c);
        g_Tfw[idx] = make_float2(c, s);
        g_TfwT[w * 16 + ky] = pk(c, s);
        g_Tsyn[w * 16 + ky] = pk(c, -s);               // e^{+i theta}
    }
    if (idx < 32 * HH) {
        int kxi = idx >> 8, h = idx & 255;
        int kx = (kxi < 16) ? kxi : (224 + kxi);       // rows 240..255
        int ph = (kx * h) & 255;
        float s, c;
        sincosf(-TWO_PI * (float)ph * (1.0f / 256.0f), &s, &c);
        g_Tfh[idx] = make_float2(c, s);
        g_Tih[idx] = make_float2(c, -s);
    }
}

// ---------------- pointwise-weight prep: (l,o,i) -> (l,i,o) dup pairs ----------------
__global__ void k_pwprep(const float* __restrict__ pww) {
    int tid = blockIdx.x * 256 + threadIdx.x;          // < NLAY*4096
    int l = tid >> 12;
    int r = tid & 4095;
    int i = r >> 6, o = r & 63;
    float w = pww[l * 4096 + o * 64 + i];
    g_pwdup[tid] = pk(w, w);
}

// ---------------- spectral-weight transpose: (l,i,o,kx,ky) -> (l,m,i,o) ----------------
__global__ void k_wt(const float* __restrict__ w1r, const float* __restrict__ w1i,
                     const float* __restrict__ w2r, const float* __restrict__ w2i) {
    int tid = blockIdx.x * blockDim.x + threadIdx.x;
    if (tid >= NLAY * 512 * WID * WID) return;
    int o   = tid & 63;
    int i   = (tid >> 6) & 63;
    int m   = (tid >> 12) & 511;
    int l   = tid >> 21;
    int kxi = m >> 4;
    int ky  = m & 15;
    int kk  = (kxi & 15) * 16 + ky;
    size_t src = ((size_t)(l * 64 + i) * 64 + o) * 256 + kk;
    float r, im;
    if (kxi < 16) { r = w1r[src]; im = w1i[src]; }
    else          { r = w2r[src]; im = w2i[src]; }
    g_Wt[tid] = make_float2(r, im);
}

// ---------------- fc0 lift: 20 -> 64 per pixel (packed pairs) ----------------
__global__ void __launch_bounds__(256) k_fc0(const float* __restrict__ x,
                                             const float* __restrict__ w,
                                             const float* __restrict__ bias) {
    __shared__ ull wp[CIN * 32];   // wp[c*32+d2] = (w[2d2][c], w[2d2+1][c])
    __shared__ ull bp[32];
    int t = threadIdx.x;
    for (int k = t; k < CIN * 32; k += 256) {
        int d2 = k & 31, c = k >> 5;
        wp[c * 32 + d2] = pk(w[(2 * d2) * CIN + c], w[(2 * d2 + 1) * CIN + c]);
    }
    if (t < 32) bp[t] = pk(bias[2 * t], bias[2 * t + 1]);
    __syncthreads();
    int p  = blockIdx.x * 256 + t;
    int b  = p >> 16;
    int sp = p & 65535;
    ull xx[CIN];
#pragma unroll
    for (int c = 0; c < CIN; c++) {
        float v = x[((size_t)(b * CIN + c) << 16) + sp];
        xx[c] = pk(v, v);
    }
#pragma unroll
    for (int d2 = 0; d2 < 32; d2++) {
        ull a = bp[d2];
#pragma unroll
        for (int c = 0; c < CIN; c++) a = ff2(xx[c], wp[c * 32 + d2], a);
        float2 f = upk(a);
        g_h0[((size_t)(b * WID + 2 * d2) << 16) + sp]     = f.x;
        g_h0[((size_t)(b * WID + 2 * d2 + 1) << 16) + sp] = f.y;
    }
}

// ---------------- forward DFT along w: 2 rows x 8 ky per thread, LDS.128 twiddles ----
// grid 1024, block 256. Block covers 256 rows.
__global__ void __launch_bounds__(256) k_dftw(const float* __restrict__ hin) {
    extern __shared__ char sm[];
    ull*   TshT = (ull*)sm;                // 4096 ull = 32 KB, [w*16+ky]
    float* xsT  = (float*)(sm + 32768);    // [16][258] = 16.5 KB
    int t = threadIdx.x;
    for (int k = t; k < 4096; k += 256) TshT[k] = g_TfwT[k];
    int kyh = t & 1;           // ky half
    int rg  = t >> 1;          // row pair 0..127
    size_t rbase = (size_t)blockIdx.x * 256;

    ull acc[2][8];
#pragma unroll
    for (int j = 0; j < 2; j++)
#pragma unroll
        for (int k = 0; k < 8; k++) acc[j][k] = 0ULL;

    for (int c = 0; c < 16; c++) {
        __syncthreads();
        for (int k = t; k < 4096; k += 256) {
            int wl = k & 15, row = k >> 4;
            xsT[wl * 258 + row] = hin[(rbase + row) * 256 + c * 16 + wl];
        }
        __syncthreads();
#pragma unroll
        for (int wl = 0; wl < 16; wl++) {
            float2 v = *(const float2*)&xsT[wl * 258 + rg * 2];
            ull v0 = pk(v.x, v.x), v1 = pk(v.y, v.y);
            const ulonglong2* tp =
                (const ulonglong2*)&TshT[(c * 16 + wl) * 16 + kyh * 8];
#pragma unroll
            for (int q = 0; q < 4; q++) {
                ulonglong2 tw = tp[q];
                acc[0][2 * q]     = ff2(v0, tw.x, acc[0][2 * q]);
                acc[0][2 * q + 1] = ff2(v0, tw.y, acc[0][2 * q + 1]);
                acc[1][2 * q]     = ff2(v1, tw.x, acc[1][2 * q]);
                acc[1][2 * q + 1] = ff2(v1, tw.y, acc[1][2 * q + 1]);
            }
        }
    }
    ull* outp = (ull*)g_Fw;
#pragma unroll
    for (int j = 0; j < 2; j++) {
        size_t r = rbase + rg * 2 + j;
        ulonglong2* op = (ulonglong2*)(outp + r * 16 + kyh * 8);
#pragma unroll
        for (int q = 0; q < 4; q++) {
            ulonglong2 st; st.x = acc[j][2 * q]; st.y = acc[j][2 * q + 1];
            op[q] = st;
        }
    }
}

// ---------------- forward DFT along h: block per (b,c), split chains ----------------
__global__ void k_dfth() {
    extern __shared__ float2 sh[];
    float2* Fsh = sh;            // 4096 = 256*16
    float2* Tsh = sh + 4096;     // 8192 = 32*256
    int t = threadIdx.x;
    int bc = blockIdx.x;
    for (int k = t; k < 4096; k += 256) Fsh[k] = g_Fw[(size_t)bc * 4096 + k];
    for (int k = t; k < 8192; k += 256) Tsh[k] = g_Tfh[k];
    __syncthreads();
#pragma unroll
    for (int mm = 0; mm < 2; mm++) {
        int m = t + mm * 256;
        int kxi = m >> 4, ky = m & 15;
        float sr0 = 0.f, si0 = 0.f, sr1 = 0.f, si1 = 0.f;
        for (int h = 0; h < 256; h += 2) {
            float2 f0  = Fsh[h * 16 + ky];
            float2 tw0 = Tsh[kxi * 256 + h];
            float2 f1  = Fsh[(h + 1) * 16 + ky];
            float2 tw1 = Tsh[kxi * 256 + h + 1];
            sr0 = fmaf(f0.x, tw0.x, fmaf(-f0.y, tw0.y, sr0));
            si0 = fmaf(f0.x, tw0.y, fmaf( f0.y, tw0.x, si0));
            sr1 = fmaf(f1.x, tw1.x, fmaf(-f1.y, tw1.y, sr1));
            si1 = fmaf(f1.x, tw1.y, fmaf( f1.y, tw1.x, si1));
        }
        g_Fm[(size_t)bc * 512 + m] = make_float2(sr0 + sr1, si0 + si1);
    }
}

// ---------------- channel mixing: block per mode ----------------
__global__ void k_mix(int layer) {
    __shared__ float2 Wm[WID * WID];   // 32 KB
    __shared__ float2 Fsh[BB * WID];   //  8 KB
    int t = threadIdx.x;
    int m = blockIdx.x;
    const float2* wsrc = g_Wt + ((size_t)layer * 512 + m) * 4096;
    for (int k = t; k < 4096; k += 256) Wm[k] = wsrc[k];
    for (int k = t; k < 1024; k += 256) {
        int b = k >> 6, i = k & 63;
        Fsh[k] = g_Fm[(size_t)(b * 64 + i) * 512 + m];
    }
    __syncthreads();
#pragma unroll
    for (int u = 0; u < 4; u++) {
        int outi = t + u * 256;
        int b = outi >> 6, o = outi & 63;
        float sr = 0.f, si = 0.f;
#pragma unroll 8
        for (int i = 0; i < 64; i++) {
            float2 f = Fsh[b * 64 + i];
            float2 w = Wm[i * 64 + o];
            sr = fmaf(f.x, w.x, fmaf(-f.y, w.y, sr));
            si = fmaf(f.x, w.y, fmaf( f.y, w.x, si));
        }
        g_Gm[(size_t)(b * 64 + o) * 512 + m] = make_float2(sr, si);
    }
}

// ---------------- inverse transform along h: packed f32x2, dup-pair G ----------------
__global__ void k_idfth() {
    extern __shared__ char shb[];
    ulonglong2* Gsh2 = (ulonglong2*)shb;          // 512 * 16B = 8 KB
    float2*     Tsh  = (float2*)(shb + 8192);     // 8192 * 8B = 64 KB
    int t = threadIdx.x;
    int bc = blockIdx.x;
    for (int k = t; k < 512; k += 256) {
        float2 g = g_Gm[(size_t)bc * 512 + k];
        ulonglong2 d; d.x = pk(g.x, g.x); d.y = pk(g.y, g.y);
        Gsh2[k] = d;
    }
    for (int k = t; k < 8192; k += 256) Tsh[k] = g_Tih[k];
    __syncthreads();
    int h = t;
    ull acc[16];
#pragma unroll
    for (int k = 0; k < 16; k++) acc[k] = 0ULL;
    for (int kxi = 0; kxi < 32; kxi++) {
        float2 tw = Tsh[kxi * 256 + h];
        ull t1 = pk(tw.x, tw.y);
        ull t2 = pk(-tw.y, tw.x);
        const ulonglong2* gp = &Gsh2[kxi * 16];
#pragma unroll
        for (int ky = 0; ky < 16; ky++) {
            ulonglong2 g = gp[ky];
            acc[ky] = ff2(g.x, t1, acc[ky]);
            acc[ky] = ff2(g.y, t2, acc[ky]);
        }
    }
    ull* outp = (ull*)(g_Gw + ((size_t)bc * 256 + h) * 16);
#pragma unroll
    for (int ky = 0; ky < 16; ky++) outp[ky] = acc[ky];
}

// ---------------- fused: inverse-w synthesis + pointwise conv + bias + gelu ----------------
// block 256 = (og 0..3) x (tw 0..63); thread handles 4 pixels x 16 out-channels.
__global__ void __launch_bounds__(256, 2)
k_fused(const float* __restrict__ hin, float* __restrict__ hout,
        int layer, const float* __restrict__ pwb, int dogelu) {
    __shared__ ull wdupT[4096];  // 32 KB: (w,w) pairs, [i*64+o] (pre-transposed)
    __shared__ ull Gd[1024];     // 8 KB: [o*16+ky] = (2gx,-2gy) (ky=0: (gx,0))
    __shared__ float bsh[64];

    int t = threadIdx.x;
    int b   = blockIdx.x >> 8;
    int row = blockIdx.x & 255;

    const ull* wsrc = g_pwdup + layer * 4096;
    for (int k = t; k < 4096; k += 256) wdupT[k] = wsrc[k];
    for (int k = t; k < 1024; k += 256) {
        int o = k >> 4, ky = k & 15;
        float2 g = g_Gw[(((size_t)(b * 64 + o)) * 256 + row) * 16 + ky];
        Gd[k] = (ky == 0) ? pk(g.x, 0.f) : pk(2.f * g.x, -2.f * g.y);
    }
    if (t < 64) bsh[t] = pwb[t];
    __syncthreads();

    int tw = t & 63, og = t >> 6;
    ull acc[16][2];
#pragma unroll
    for (int oo = 0; oo < 16; oo++) {
        float bv = bsh[og * 16 + oo];
        acc[oo][0] = pk(bv, bv);
        acc[oo][1] = pk(bv, bv);
    }

    size_t base = ((size_t)(b * 64) << 16) + (row << 8) + tw * 4;
    for (int i = 0; i < 64; i++) {
        ulonglong2 xv = *(const ulonglong2*)(hin + base + ((size_t)i << 16));
        const ulonglong2* wp = (const ulonglong2*)&wdupT[i * 64 + og * 16];
#pragma unroll
        for (int j = 0; j < 8; j++) {
            ulonglong2 wd = wp[j];
            acc[2 * j][0]     = ff2(xv.x, wd.x, acc[2 * j][0]);
            acc[2 * j][1]     = ff2(xv.y, wd.x, acc[2 * j][1]);
            acc[2 * j + 1][0] = ff2(xv.x, wd.y, acc[2 * j + 1][0]);
            acc[2 * j + 1][1] = ff2(xv.y, wd.y, acc[2 * j + 1][1]);
        }
    }

    const float invn = 1.0f / 65536.0f;
#pragma unroll
    for (int q = 0; q < 4; q++) {
        int w = tw * 4 + q;
        const ulonglong2* tp = (const ulonglong2*)&g_Tsyn[w * 16];
        ulonglong2 tw0 = tp[0], tw1 = tp[1], tw2 = tp[2], tw3 = tp[3];
        ulonglong2 tw4 = tp[4], tw5 = tp[5], tw6 = tp[6], tw7 = tp[7];
        int p = q >> 1, lane = q & 1;
#pragma unroll
        for (int oo = 0; oo < 16; oo++) {
            const ulonglong2* gp = (const ulonglong2*)&Gd[(og * 16 + oo) << 4];
            ull xa = 0ULL, xb = 0ULL;
            ulonglong2 g0 = gp[0], g1 = gp[1], g2 = gp[2], g3 = gp[3];
            xa = ff2(g0.x, tw0.x, xa); xb = ff2(g0.y, tw0.y, xb);
            xa = ff2(g1.x, tw1.x, xa); xb = ff2(g1.y, tw1.y, xb);
            xa = ff2(g2.x, tw2.x, xa); xb = ff2(g2.y, tw2.y, xb);
            xa = ff2(g3.x, tw3.x, xa); xb = ff2(g3.y, tw3.y, xb);
            ulonglong2 g4 = gp[4], g5 = gp[5], g6 = gp[6], g7 = gp[7];
            xa = ff2(g4.x, tw4.x, xa); xb = ff2(g4.y, tw4.y, xb);
            xa = ff2(g5.x, tw5.x, xa); xb = ff2(g5.y, tw5.y, xb);
            xa = ff2(g6.x, tw6.x, xa); xb = ff2(g6.y, tw6.y, xb);
            xa = ff2(g7.x, tw7.x, xa); xb = ff2(g7.y, tw7.y, xb);
            float2 xfa = upk(xa), xfb = upk(xb);
            float x1 = (xfa.x + xfa.y) + (xfb.x + xfb.y);
            float2 a = upk(acc[oo][p]);
            float v = fmaf(x1, invn, lane ? a.y : a.x);
            if (dogelu) v = gelu_fast(v);
            if (lane) a.y = v; else a.x = v;
            acc[oo][p] = pk(a.x, a.y);
        }
    }

#pragma unroll
    for (int oo = 0; oo < 16; oo++) {
        int o = og * 16 + oo;
        ulonglong2 st; st.x = acc[oo][0]; st.y = acc[oo][1];
        *(ulonglong2*)(hout + ((size_t)(b * 64 + o) << 16) + (row << 8) + tw * 4) = st;
    }
}

// ---------------- fused projection: 64 -> 128 (gelu) -> 20, packed pairs ----------------
__global__ void __launch_bounds__(256, 2)
k_final(const float* __restrict__ hin, float* __restrict__ out,
        const float* __restrict__ w1, const float* __restrict__ b1,
        const float* __restrict__ w2, const float* __restrict__ b2) {
    __shared__ ull w1p[FCH * 32];     // 32 KB: u64 view of w1 (pairs over in-ch)
    __shared__ ull w2t[FCH * 10];     // 10 KB: [j*10+o2] = (w2[2o2][j], w2[2o2+1][j])
    __shared__ float b1sh[FCH];
    __shared__ ull b2p[10];
    int t = threadIdx.x;
    for (int k = t; k < FCH * 32; k += 256) w1p[k] = ((const ull*)w1)[k];
    for (int k = t; k < FCH * 10; k += 256) {
        int o2 = k >> 7, j = k & 127;
        w2t[j * 10 + o2] = pk(w2[(2 * o2) * FCH + j], w2[(2 * o2 + 1) * FCH + j]);
    }
    if (t < FCH) b1sh[t] = b1[t];
    if (t < 10)  b2p[t] = pk(b2[2 * t], b2[2 * t + 1]);
    __syncthreads();

    int b   = blockIdx.x >> 8;
    int row = blockIdx.x & 255;
    size_t sp = ((size_t)row << 8) + t;
    size_t base = ((size_t)(b * WID) << 16) + sp;
    ull xv[32];
#pragma unroll
    for (int i2 = 0; i2 < 32; i2++)
        xv[i2] = pk(hin[base + ((size_t)(2 * i2) << 16)],
                    hin[base + ((size_t)(2 * i2 + 1) << 16)]);
    ull acc[10];
#pragma unroll
    for (int o2 = 0; o2 < 10; o2++) acc[o2] = b2p[o2];

    for (int j = 0; j < FCH; j++) {
        const ulonglong2* wp = (const ulonglong2*)&w1p[j * 32];
        ull ha = 0ULL, hb = 0ULL, hc = 0ULL, hd = 0ULL;
#pragma unroll
        for (int k = 0; k < 4; k++) {
            ulonglong2 u0 = wp[4 * k], u1 = wp[4 * k + 1];
            ulonglong2 u2 = wp[4 * k + 2], u3 = wp[4 * k + 3];
            ha = ff2(xv[8 * k],     u0.x, ha); ha = ff2(xv[8 * k + 1], u0.y, ha);
            hb = ff2(xv[8 * k + 2], u1.x, hb); hb = ff2(xv[8 * k + 3], u1.y, hb);
            hc = ff2(xv[8 * k + 4], u2.x, hc); hc = ff2(xv[8 * k + 5], u2.y, hc);
            hd = ff2(xv[8 * k + 6], u3.x, hd); hd = ff2(xv[8 * k + 7], u3.y, hd);
        }
        float2 fa = upk(ha), fb = upk(hb), fc = upk(hc), fd = upk(hd);
        float hv = gelu_fast(((fa.x + fa.y) + (fb.x + fb.y)) +
                             ((fc.x + fc.y) + (fd.x + fd.y)) + b1sh[j]);
        ull hh = pk(hv, hv);
        const ulonglong2* w2p = (const ulonglong2*)&w2t[j * 10];
#pragma unroll
        for (int k = 0; k < 5; k++) {
            ulonglong2 u = w2p[k];
            acc[2 * k]     = ff2(hh, u.x, acc[2 * k]);
            acc[2 * k + 1] = ff2(hh, u.y, acc[2 * k + 1]);
        }
    }
#pragma unroll
    for (int o2 = 0; o2 < 10; o2++) {
        float2 a = upk(acc[o2]);
        out[((size_t)(b * CO + 2 * o2) << 16) + sp]     = a.x;
        out[((size_t)(b * CO + 2 * o2 + 1) << 16) + sp] = a.y;
    }
}

// ---------------- orchestration ----------------
extern "C" void kernel_launch(void* const* d_in, const int* in_sizes, int n_in,
                              void* d_out, int out_size) {
    const float* x    = (const float*)d_in[0];
    const float* w1r  = (const float*)d_in[1];
    const float* w1i  = (const float*)d_in[2];
    const float* w2r  = (const float*)d_in[3];
    const float* w2i  = (const float*)d_in[4];
    const float* pww  = (const float*)d_in[5];
    const float* pwb  = (const float*)d_in[6];
    const float* fc0w = (const float*)d_in[7];
    const float* fc0b = (const float*)d_in[8];
    const float* fc1w = (const float*)d_in[9];
    const float* fc1b = (const float*)d_in[10];
    const float* fc2w = (const float*)d_in[11];
    const float* fc2b = (const float*)d_in[12];
    float* out = (float*)d_out;

    cudaFuncSetAttribute(k_dftw,  cudaFuncAttributeMaxDynamicSharedMemorySize, 49280);
    cudaFuncSetAttribute(k_dfth,  cudaFuncAttributeMaxDynamicSharedMemorySize, 98304);
    cudaFuncSetAttribute(k_idfth, cudaFuncAttributeMaxDynamicSharedMemorySize, 73728);

    void *p0, *p1;
    cudaGetSymbolAddress(&p0, g_h0);
    cudaGetSymbolAddress(&p1, g_h1);
    float* hb[2] = {(float*)p0, (float*)p1};

    k_twiddle<<<32, 256>>>();
    k_pwprep<<<NLAY * 4096 / 256, 256>>>(pww);
    k_wt<<<(NLAY * 512 * WID * WID) / 256, 256>>>(w1r, w1i, w2r, w2i);
    k_fc0<<<NPIX / 256, 256>>>(x, fc0w, fc0b);

    for (int l = 0; l < NLAY; l++) {
        const float* hi = hb[l & 1];
        float*       ho = hb[(l + 1) & 1];
        k_dftw<<<1024, 256, 49280>>>(hi);
        k_dfth<<<1024, 256, 98304>>>();
        k_mix<<<512, 256>>>(l);
        k_idfth<<<1024, 256, 73728>>>();
        k_fused<<<4096, 256>>>(hi, ho, l, pwb + (size_t)l * WID,
                               (l < NLAY - 1) ? 1 : 0);
    }
    k_final<<<4096, 256>>>(hb[0], out, fc1w, fc1b, fc2w, fc2b);
}

// round 9
// speedup vs baseline: 1.0124x; 1.0124x over previous
#include <cuda_runtime.h>
#include <math.h>

#define BB 16
#define CIN 20
#define HH 256
#define WW 256
#define WID 64
#define M1V 16
#define M2V 16
#define NLAY 4
#define FCH 128
#define CO 20
#define HW 65536
#define NPIX (BB*HW)

#define TWO_PI 6.28318530717958647692f

typedef unsigned long long ull;

// ---------------- scratch (device globals; no allocations allowed) ----------------
__device__ float  g_h0[(size_t)BB*WID*HW];            // 268 MB ping
__device__ float  g_h1[(size_t)BB*WID*HW];            // 268 MB pong
__device__ float2 g_Fw[(size_t)BB*WID*HH*M2V];        // (b,c,h,ky)  33.5 MB
__device__ float2 g_Fm[(size_t)BB*WID*32*M2V];        // (b,c,kxi,ky) 4 MB
__device__ float2 g_Gm[(size_t)BB*WID*32*M2V];        // 4 MB
__device__ float2 g_Gw[(size_t)BB*WID*HH*M2V];        // (b,c,h,ky)  33.5 MB
__device__ float2 g_Wt[(size_t)NLAY*512*WID*WID];     // (l,m,i,o)   67 MB
__device__ float2 g_Tfw[M2V*WW];                      // e^{-2pi i ky w/256}, [ky*256+w]
__device__ ull    g_TfwT[WW*M2V];                     // same, transposed [w*16+ky]
__device__ ull    g_Tsyn[WW*M2V];                     // e^{+2pi i ky w/256}, [w*16+ky]
__device__ float2 g_Tfh[32*HH];                       // e^{-2pi i kx h/256}, kx in R
__device__ float2 g_Tih[32*HH];                       // conj of above

// ---- packed f32x2 helpers ----
__device__ __forceinline__ ull ff2(ull a, ull b, ull c) {
    ull d; asm("fma.rn.f32x2 %0,%1,%2,%3;" : "=l"(d) : "l"(a), "l"(b), "l"(c)); return d;
}
__device__ __forceinline__ ull pk(float x, float y) {
    ull d; asm("mov.b64 %0,{%1,%2};" : "=l"(d) : "f"(x), "f"(y)); return d;
}
__device__ __forceinline__ float2 upk(ull u) {
    float2 f; asm("mov.b64 {%0,%1},%2;" : "=f"(f.x), "=f"(f.y) : "l"(u)); return f;
}

// ---- fast erf-based gelu (Abramowitz-Stegun 7.1.26, |eps|<=1.5e-7) ----
__device__ __forceinline__ float gelu_fast(float v) {
    float z  = 0.70710678118654752440f * v;
    float az = fabsf(z);
    float t  = __fdividef(1.0f, fmaf(0.3275911f, az, 1.0f));
    float e  = __expf(-az * az);
    float p  = t * (0.254829592f + t * (-0.284496736f + t * (1.421413741f +
               t * (-1.453152027f + t * 1.061405429f))));
    float er = fmaf(-p, e, 1.0f);
    er = copysignf(er, z);
    return 0.5f * v * (1.0f + er);
}

// ---------------- twiddle init ----------------
__global__ void k_twiddle() {
    int idx = blockIdx.x * blockDim.x + threadIdx.x;   // 8192 threads
    if (idx < M2V * WW) {
        int ky = idx >> 8, w = idx & 255;
        int ph = (ky * w) & 255;                       // exact phase mod 256
        float s, c;
        sincosf(-TWO_PI * (float)ph * (1.0f / 256.0f), &s, &c);
        g_Tfw[idx] = make_float2(c, s);
        g_TfwT[w * 16 + ky] = pk(c, s);
        g_Tsyn[w * 16 + ky] = pk(c, -s);               // e^{+i theta}
    }
    if (idx < 32 * HH) {
        int kxi = idx >> 8, h = idx & 255;
        int kx = (kxi < 16) ? kxi : (224 + kxi);       // rows 240..255
        int ph = (kx * h) & 255;
        float s, c;
        sincosf(-TWO_PI * (float)ph * (1.0f / 256.0f), &s, &c);
        g_Tfh[idx] = make_float2(c, s);
        g_Tih[idx] = make_float2(c, -s);
    }
}

// ---------------- spectral-weight transpose: (l,i,o,kx,ky) -> (l,m,i,o) ----------------
__global__ void k_wt(const float* __restrict__ w1r, const float* __restrict__ w1i,
                     const float* __restrict__ w2r, const float* __restrict__ w2i) {
    int tid = blockIdx.x * blockDim.x + threadIdx.x;
    if (tid >= NLAY * 512 * WID * WID) return;
    int o   = tid & 63;
    int i   = (tid >> 6) & 63;
    int m   = (tid >> 12) & 511;
    int l   = tid >> 21;
    int kxi = m >> 4;
    int ky  = m & 15;
    int kk  = (kxi & 15) * 16 + ky;
    size_t src = ((size_t)(l * 64 + i) * 64 + o) * 256 + kk;
    float r, im;
    if (kxi < 16) { r = w1r[src]; im = w1i[src]; }
    else          { r = w2r[src]; im = w2i[src]; }
    g_Wt[tid] = make_float2(r, im);
}

// ---------------- fc0 lift: 20 -> 64 per pixel (packed pairs) ----------------
__global__ void __launch_bounds__(256) k_fc0(const float* __restrict__ x,
                                             const float* __restrict__ w,
                                             const float* __restrict__ bias) {
    __shared__ ull wp[CIN * 32];   // wp[c*32+d2] = (w[2d2][c], w[2d2+1][c])
    __shared__ ull bp[32];
    int t = threadIdx.x;
    for (int k = t; k < CIN * 32; k += 256) {
        int d2 = k & 31, c = k >> 5;
        wp[c * 32 + d2] = pk(w[(2 * d2) * CIN + c], w[(2 * d2 + 1) * CIN + c]);
    }
    if (t < 32) bp[t] = pk(bias[2 * t], bias[2 * t + 1]);
    __syncthreads();
    int p  = blockIdx.x * 256 + t;
    int b  = p >> 16;
    int sp = p & 65535;
    ull xx[CIN];
#pragma unroll
    for (int c = 0; c < CIN; c++) {
        float v = x[((size_t)(b * CIN + c) << 16) + sp];
        xx[c] = pk(v, v);
    }
#pragma unroll
    for (int d2 = 0; d2 < 32; d2++) {
        ull a = bp[d2];
#pragma unroll
        for (int c = 0; c < CIN; c++) a = ff2(xx[c], wp[c * 32 + d2], a);
        float2 f = upk(a);
        g_h0[((size_t)(b * WID + 2 * d2) << 16) + sp]     = f.x;
        g_h0[((size_t)(b * WID + 2 * d2 + 1) << 16) + sp] = f.y;
    }
}

// ---------------- forward DFT along w: 2 rows x 8 ky per thread, LDS.128 twiddles ----
// grid 1024, block 256. Block covers 256 rows.
__global__ void __launch_bounds__(256) k_dftw(const float* __restrict__ hin) {
    extern __shared__ char sm[];
    ull*   TshT = (ull*)sm;                // 4096 ull = 32 KB, [w*16+ky]
    float* xsT  = (float*)(sm + 32768);    // [16][258] = 16.5 KB
    int t = threadIdx.x;
    for (int k = t; k < 4096; k += 256) TshT[k] = g_TfwT[k];
    int kyh = t & 1;           // ky half
    int rg  = t >> 1;          // row pair 0..127
    size_t rbase = (size_t)blockIdx.x * 256;

    ull acc[2][8];
#pragma unroll
    for (int j = 0; j < 2; j++)
#pragma unroll
        for (int k = 0; k < 8; k++) acc[j][k] = 0ULL;

    for (int c = 0; c < 16; c++) {
        __syncthreads();
        for (int k = t; k < 4096; k += 256) {
            int wl = k & 15, row = k >> 4;
            xsT[wl * 258 + row] = hin[(rbase + row) * 256 + c * 16 + wl];
        }
        __syncthreads();
#pragma unroll
        for (int wl = 0; wl < 16; wl++) {
            float2 v = *(const float2*)&xsT[wl * 258 + rg * 2];
            ull v0 = pk(v.x, v.x), v1 = pk(v.y, v.y);
            const ulonglong2* tp =
                (const ulonglong2*)&TshT[(c * 16 + wl) * 16 + kyh * 8];
#pragma unroll
            for (int q = 0; q < 4; q++) {
                ulonglong2 tw = tp[q];
                acc[0][2 * q]     = ff2(v0, tw.x, acc[0][2 * q]);
                acc[0][2 * q + 1] = ff2(v0, tw.y, acc[0][2 * q + 1]);
                acc[1][2 * q]     = ff2(v1, tw.x, acc[1][2 * q]);
                acc[1][2 * q + 1] = ff2(v1, tw.y, acc[1][2 * q + 1]);
            }
        }
    }
    ull* outp = (ull*)g_Fw;
#pragma unroll
    for (int j = 0; j < 2; j++) {
        size_t r = rbase + rg * 2 + j;
        ulonglong2* op = (ulonglong2*)(outp + r * 16 + kyh * 8);
#pragma unroll
        for (int q = 0; q < 4; q++) {
            ulonglong2 st; st.x = acc[j][2 * q]; st.y = acc[j][2 * q + 1];
            op[q] = st;
        }
    }
}

// ---------------- forward DFT along h: block per (b,c) ----------------
__global__ void k_dfth() {
    extern __shared__ float2 sh[];
    float2* Fsh = sh;            // 4096 = 256*16
    float2* Tsh = sh + 4096;     // 8192 = 32*256
    int t = threadIdx.x;
    int bc = blockIdx.x;
    for (int k = t; k < 4096; k += 256) Fsh[k] = g_Fw[(size_t)bc * 4096 + k];
    for (int k = t; k < 8192; k += 256) Tsh[k] = g_Tfh[k];
    __syncthreads();
#pragma unroll
    for (int mm = 0; mm < 2; mm++) {
        int m = t + mm * 256;
        int kxi = m >> 4, ky = m & 15;
        float sr = 0.f, si = 0.f;
        for (int h = 0; h < 256; h++) {
            float2 f  = Fsh[h * 16 + ky];
            float2 tw = Tsh[kxi * 256 + h];
            sr = fmaf(f.x, tw.x, fmaf(-f.y, tw.y, sr));
            si = fmaf(f.x, tw.y, fmaf( f.y, tw.x, si));
        }
        g_Fm[(size_t)bc * 512 + m] = make_float2(sr, si);
    }
}

// ---------------- channel mixing: block per mode ----------------
__global__ void k_mix(int layer) {
    __shared__ float2 Wm[WID * WID];   // 32 KB
    __shared__ float2 Fsh[BB * WID];   //  8 KB
    int t = threadIdx.x;
    int m = blockIdx.x;
    const float2* wsrc = g_Wt + ((size_t)layer * 512 + m) * 4096;
    for (int k = t; k < 4096; k += 256) Wm[k] = wsrc[k];
    for (int k = t; k < 1024; k += 256) {
        int b = k >> 6, i = k & 63;
        Fsh[k] = g_Fm[(size_t)(b * 64 + i) * 512 + m];
    }
    __syncthreads();
#pragma unroll
    for (int u = 0; u < 4; u++) {
        int outi = t + u * 256;
        int b = outi >> 6, o = outi & 63;
        float sr = 0.f, si = 0.f;
#pragma unroll 8
        for (int i = 0; i < 64; i++) {
            float2 f = Fsh[b * 64 + i];
            float2 w = Wm[i * 64 + o];
            sr = fmaf(f.x, w.x, fmaf(-f.y, w.y, sr));
            si = fmaf(f.x, w.y, fmaf( f.y, w.x, si));
        }
        g_Gm[(size_t)(b * 64 + o) * 512 + m] = make_float2(sr, si);
    }
}

// ---------------- inverse transform along h: packed f32x2, dup-pair G ----------------
__global__ void k_idfth() {
    extern __shared__ char shb[];
    ulonglong2* Gsh2 = (ulonglong2*)shb;          // 512 * 16B = 8 KB
    float2*     Tsh  = (float2*)(shb + 8192);     // 8192 * 8B = 64 KB
    int t = threadIdx.x;
    int bc = blockIdx.x;
    for (int k = t; k < 512; k += 256) {
        float2 g = g_Gm[(size_t)bc * 512 + k];
        ulonglong2 d; d.x = pk(g.x, g.x); d.y = pk(g.y, g.y);
        Gsh2[k] = d;
    }
    for (int k = t; k < 8192; k += 256) Tsh[k] = g_Tih[k];
    __syncthreads();
    int h = t;
    ull acc[16];
#pragma unroll
    for (int k = 0; k < 16; k++) acc[k] = 0ULL;
    for (int kxi = 0; kxi < 32; kxi++) {
        float2 tw = Tsh[kxi * 256 + h];
        ull t1 = pk(tw.x, tw.y);
        ull t2 = pk(-tw.y, tw.x);
        const ulonglong2* gp = &Gsh2[kxi * 16];
#pragma unroll
        for (int ky = 0; ky < 16; ky++) {
            ulonglong2 g = gp[ky];
            acc[ky] = ff2(g.x, t1, acc[ky]);
            acc[ky] = ff2(g.y, t2, acc[ky]);
        }
    }
    ull* outp = (ull*)(g_Gw + ((size_t)bc * 256 + h) * 16);
#pragma unroll
    for (int ky = 0; ky < 16; ky++) outp[ky] = acc[ky];
}

// ---------------- fused: inverse-w synthesis + pointwise conv + bias + gelu ----------------
// block 256 = (og 0..3) x (tw 0..63); thread handles 4 pixels x 16 out-channels.
__global__ void __launch_bounds__(256, 2)
k_fused(const float* __restrict__ hin, float* __restrict__ hout,
        const float* __restrict__ pww, const float* __restrict__ pwb, int dogelu) {
    __shared__ ull wdupT[4096];  // 32 KB: (w,w) pairs, TRANSPOSED [i*64+o]
    __shared__ ull Gd[1024];     // 8 KB: [o*16+ky] = (2gx,-2gy) (ky=0: (gx,0))
    __shared__ float bsh[64];

    int t = threadIdx.x;
    int b   = blockIdx.x >> 8;
    int row = blockIdx.x & 255;

    for (int k = t; k < 4096; k += 256) {
        int o = k & 63, i = k >> 6;
        float w = pww[o * 64 + i];
        wdupT[k] = pk(w, w);
    }
    for (int k = t; k < 1024; k += 256) {
        int o = k >> 4, ky = k & 15;
        float2 g = g_Gw[(((size_t)(b * 64 + o)) * 256 + row) * 16 + ky];
        Gd[k] = (ky == 0) ? pk(g.x, 0.f) : pk(2.f * g.x, -2.f * g.y);
    }
    if (t < 64) bsh[t] = pwb[t];
    __syncthreads();

    int tw = t & 63, og = t >> 6;
    ull acc[16][2];
#pragma unroll
    for (int oo = 0; oo < 16; oo++) {
        float bv = bsh[og * 16 + oo];
        acc[oo][0] = pk(bv, bv);
        acc[oo][1] = pk(bv, bv);
    }

    size_t base = ((size_t)(b * 64) << 16) + (row << 8) + tw * 4;
    for (int i = 0; i < 64; i++) {
        ulonglong2 xv = *(const ulonglong2*)(hin + base + ((size_t)i << 16));
        const ulonglong2* wp = (const ulonglong2*)&wdupT[i * 64 + og * 16];
#pragma unroll
        for (int j = 0; j < 8; j++) {
            ulonglong2 wd = wp[j];
            acc[2 * j][0]     = ff2(xv.x, wd.x, acc[2 * j][0]);
            acc[2 * j][1]     = ff2(xv.y, wd.x, acc[2 * j][1]);
            acc[2 * j + 1][0] = ff2(xv.x, wd.y, acc[2 * j + 1][0]);
            acc[2 * j + 1][1] = ff2(xv.y, wd.y, acc[2 * j + 1][1]);
        }
    }

    const float invn = 1.0f / 65536.0f;
#pragma unroll
    for (int q = 0; q < 4; q++) {
        int w = tw * 4 + q;
        const ulonglong2* tp = (const ulonglong2*)&g_Tsyn[w * 16];
        ulonglong2 tw0 = tp[0], tw1 = tp[1], tw2 = tp[2], tw3 = tp[3];
        ulonglong2 tw4 = tp[4], tw5 = tp[5], tw6 = tp[6], tw7 = tp[7];
        int p = q >> 1, lane = q & 1;
#pragma unroll
        for (int oo = 0; oo < 16; oo++) {
            const ulonglong2* gp = (const ulonglong2*)&Gd[(og * 16 + oo) << 4];
            ull xa = 0ULL, xb = 0ULL;
            ulonglong2 g0 = gp[0], g1 = gp[1], g2 = gp[2], g3 = gp[3];
            xa = ff2(g0.x, tw0.x, xa); xb = ff2(g0.y, tw0.y, xb);
            xa = ff2(g1.x, tw1.x, xa); xb = ff2(g1.y, tw1.y, xb);
            xa = ff2(g2.x, tw2.x, xa); xb = ff2(g2.y, tw2.y, xb);
            xa = ff2(g3.x, tw3.x, xa); xb = ff2(g3.y, tw3.y, xb);
            ulonglong2 g4 = gp[4], g5 = gp[5], g6 = gp[6], g7 = gp[7];
            xa = ff2(g4.x, tw4.x, xa); xb = ff2(g4.y, tw4.y, xb);
            xa = ff2(g5.x, tw5.x, xa); xb = ff2(g5.y, tw5.y, xb);
            xa = ff2(g6.x, tw6.x, xa); xb = ff2(g6.y, tw6.y, xb);
            xa = ff2(g7.x, tw7.x, xa); xb = ff2(g7.y, tw7.y, xb);
            float2 xfa = upk(xa), xfb = upk(xb);
            float x1 = (xfa.x + xfa.y) + (xfb.x + xfb.y);
            float2 a = upk(acc[oo][p]);
            float v = fmaf(x1, invn, lane ? a.y : a.x);
            if (dogelu) v = gelu_fast(v);
            if (lane) a.y = v; else a.x = v;
            acc[oo][p] = pk(a.x, a.y);
        }
    }

#pragma unroll
    for (int oo = 0; oo < 16; oo++) {
        int o = og * 16 + oo;
        ulonglong2 st; st.x = acc[oo][0]; st.y = acc[oo][1];
        *(ulonglong2*)(hout + ((size_t)(b * 64 + o) << 16) + (row << 8) + tw * 4) = st;
    }
}

// ---------------- fused projection: 64 -> 128 (gelu) -> 20, packed pairs ----------------
__global__ void __launch_bounds__(256, 2)
k_final(const float* __restrict__ hin, float* __restrict__ out,
        const float* __restrict__ w1, const float* __restrict__ b1,
        const float* __restrict__ w2, const float* __restrict__ b2) {
    __shared__ ull w1p[FCH * 32];     // 32 KB: u64 view of w1 (pairs over in-ch)
    __shared__ ull w2t[FCH * 10];     // 10 KB: [j*10+o2] = (w2[2o2][j], w2[2o2+1][j])
    __shared__ float b1sh[FCH];
    __shared__ ull b2p[10];
    int t = threadIdx.x;
    for (int k = t; k < FCH * 32; k += 256) w1p[k] = ((const ull*)w1)[k];
    for (int k = t; k < FCH * 10; k += 256) {
        int o2 = k >> 7, j = k & 127;
        w2t[j * 10 + o2] = pk(w2[(2 * o2) * FCH + j], w2[(2 * o2 + 1) * FCH + j]);
    }
    if (t < FCH) b1sh[t] = b1[t];
    if (t < 10)  b2p[t] = pk(b2[2 * t], b2[2 * t + 1]);
    __syncthreads();

    int b   = blockIdx.x >> 8;
    int row = blockIdx.x & 255;
    size_t sp = ((size_t)row << 8) + t;
    size_t base = ((size_t)(b * WID) << 16) + sp;
    ull xv[32];
#pragma unroll
    for (int i2 = 0; i2 < 32; i2++)
        xv[i2] = pk(hin[base + ((size_t)(2 * i2) << 16)],
                    hin[base + ((size_t)(2 * i2 + 1) << 16)]);
    ull acc[10];
#pragma unroll
    for (int o2 = 0; o2 < 10; o2++) acc[o2] = b2p[o2];

    for (int j = 0; j < FCH; j++) {
        const ulonglong2* wp = (const ulonglong2*)&w1p[j * 32];
        ull h2 = 0ULL;
#pragma unroll
        for (int k = 0; k < 16; k++) {
            ulonglong2 u = wp[k];
            h2 = ff2(xv[2 * k], u.x, h2);
            h2 = ff2(xv[2 * k + 1], u.y, h2);
        }
        float2 hf = upk(h2);
        float hv = gelu_fast(hf.x + hf.y + b1sh[j]);
        ull hh = pk(hv, hv);
        const ulonglong2* w2p = (const ulonglong2*)&w2t[j * 10];
#pragma unroll
        for (int k = 0; k < 5; k++) {
            ulonglong2 u = w2p[k];
            acc[2 * k]     = ff2(hh, u.x, acc[2 * k]);
            acc[2 * k + 1] = ff2(hh, u.y, acc[2 * k + 1]);
        }
    }
#pragma unroll
    for (int o2 = 0; o2 < 10; o2++) {
        float2 a = upk(acc[o2]);
        out[((size_t)(b * CO + 2 * o2) << 16) + sp]     = a.x;
        out[((size_t)(b * CO + 2 * o2 + 1) << 16) + sp] = a.y;
    }
}

// ---------------- orchestration ----------------
extern "C" void kernel_launch(void* const* d_in, const int* in_sizes, int n_in,
                              void* d_out, int out_size) {
    const float* x    = (const float*)d_in[0];
    const float* w1r  = (const float*)d_in[1];
    const float* w1i  = (const float*)d_in[2];
    const float* w2r  = (const float*)d_in[3];
    const float* w2i  = (const float*)d_in[4];
    const float* pww  = (const float*)d_in[5];
    const float* pwb  = (const float*)d_in[6];
    const float* fc0w = (const float*)d_in[7];
    const float* fc0b = (const float*)d_in[8];
    const float* fc1w = (const float*)d_in[9];
    const float* fc1b = (const float*)d_in[10];
    const float* fc2w = (const float*)d_in[11];
    const float* fc2b = (const float*)d_in[12];
    float* out = (float*)d_out;

    cudaFuncSetAttribute(k_dftw,  cudaFuncAttributeMaxDynamicSharedMemorySize, 49280);
    cudaFuncSetAttribute(k_dfth,  cudaFuncAttributeMaxDynamicSharedMemorySize, 98304);
    cudaFuncSetAttribute(k_idfth, cudaFuncAttributeMaxDynamicSharedMemorySize, 73728);

    void *p0, *p1;
    cudaGetSymbolAddress(&p0, g_h0);
    cudaGetSymbolAddress(&p1, g_h1);
    float* hb[2] = {(float*)p0, (float*)p1};

    k_twiddle<<<32, 256>>>();
    k_wt<<<(NLAY * 512 * WID * WID) / 256, 256>>>(w1r, w1i, w2r, w2i);
    k_fc0<<<NPIX / 256, 256>>>(x, fc0w, fc0b);

    for (int l = 0; l < NLAY; l++) {
        const float* hi = hb[l & 1];
        float*       ho = hb[(l + 1) & 1];
        k_dftw<<<1024, 256, 49280>>>(hi);
        k_dfth<<<1024, 256, 98304>>>();
        k_mix<<<512, 256>>>(l);
        k_idfth<<<1024, 256, 73728>>>();
        k_fused<<<4096, 256>>>(hi, ho, pww + (size_t)l * WID * WID,
                               pwb + (size_t)l * WID, (l < NLAY - 1) ? 1 : 0);
    }
    k_final<<<4096, 256>>>(hb[0], out, fc1w, fc1b, fc2w, fc2b);
}

// round 12
// speedup vs baseline: 2.8918x; 2.8565x over previous
#include <cuda_runtime.h>
#include <cuda_bf16.h>
#include <math.h>
#include <stdint.h>

#define BB 16
#define CIN 20
#define HH 256
#define WW 256
#define WID 64
#define M1V 16
#define M2V 16
#define NLAY 4
#define FCH 128
#define CO 20
#define HW 65536
#define NPIX (BB*HW)

#define TWO_PI 6.28318530717958647692f

typedef unsigned long long ull;

// ---------------- scratch (device globals; no allocations allowed) ----------------
__device__ float  g_h0[(size_t)BB*WID*HW];            // 268 MB ping
__device__ float  g_h1[(size_t)BB*WID*HW];            // 268 MB pong
__device__ float2 g_Fw[(size_t)BB*WID*HH*M2V];        // (b,c,h,ky)  33.5 MB
__device__ float2 g_Fm[(size_t)BB*WID*32*M2V];        // (b,c,kxi,ky) 4 MB
__device__ float2 g_Gm[(size_t)BB*WID*32*M2V];        // 4 MB
__device__ float2 g_Gw[(size_t)BB*WID*HH*M2V];        // (b,c,h,ky)  33.5 MB
__device__ float2 g_Wt[(size_t)NLAY*512*WID*WID];     // (l,m,i,o)   67 MB
__device__ ull    g_TfwT[WW*M2V];                     // fwd twiddles [w*16+ky]
__device__ float2 g_Tfh[32*HH];                       // e^{-2pi i kx h/256}
__device__ float2 g_Tih[32*HH];                       // conj
// bf16 prepped tables (pre-swizzled byte layouts)
__device__ __align__(16) unsigned char g_TsbH[16384]; // synth T hi: [px][32k] SW64
__device__ __align__(16) unsigned char g_TsbL[16384]; // synth T lo
__device__ __align__(16) unsigned char g_WbH[NLAY*8192]; // conv W hi: [och][64ch] SW128
__device__ __align__(16) unsigned char g_WbL[NLAY*8192];

// ---- packed f32x2 helpers ----
__device__ __forceinline__ ull ff2(ull a, ull b, ull c) {
    ull d; asm("fma.rn.f32x2 %0,%1,%2,%3;" : "=l"(d) : "l"(a), "l"(b), "l"(c)); return d;
}
__device__ __forceinline__ ull pk(float x, float y) {
    ull d; asm("mov.b64 %0,{%1,%2};" : "=l"(d) : "f"(x), "f"(y)); return d;
}
__device__ __forceinline__ float2 upk(ull u) {
    float2 f; asm("mov.b64 {%0,%1},%2;" : "=f"(f.x), "=f"(f.y) : "l"(u)); return f;
}

// ---- fast erf-based gelu ----
__device__ __forceinline__ float gelu_fast(float v) {
    float z  = 0.70710678118654752440f * v;
    float az = fabsf(z);
    float t  = __fdividef(1.0f, fmaf(0.3275911f, az, 1.0f));
    float e  = __expf(-az * az);
    float p  = t * (0.254829592f + t * (-0.284496736f + t * (1.421413741f +
               t * (-1.453152027f + t * 1.061405429f))));
    float er = fmaf(-p, e, 1.0f);
    er = copysignf(er, z);
    return 0.5f * v * (1.0f + er);
}

#define SW128(x) ((x) ^ (((x) >> 3) & 0x70))
#define SW64(x)  ((x) ^ (((x) >> 3) & 0x30))

__device__ __forceinline__ uint32_t smem_u32(const void* p) {
    uint32_t a;
    asm("{ .reg .u64 t; cvta.to.shared.u64 t, %1; cvt.u32.u64 %0, t; }" : "=r"(a) : "l"(p));
    return a;
}
__device__ __forceinline__ void ldsm4(uint32_t& r0, uint32_t& r1, uint32_t& r2, uint32_t& r3,
                                      uint32_t a) {
    asm volatile("ldmatrix.sync.aligned.m8n8.x4.shared.b16 {%0,%1,%2,%3}, [%4];"
                 : "=r"(r0), "=r"(r1), "=r"(r2), "=r"(r3) : "r"(a));
}
__device__ __forceinline__ void mma16816(float* c, const uint32_t* a, const uint32_t* b) {
    asm volatile(
        "mma.sync.aligned.m16n8k16.row.col.f32.bf16.bf16.f32 "
        "{%0,%1,%2,%3}, {%4,%5,%6,%7}, {%8,%9}, {%0,%1,%2,%3};"
        : "+f"(c[0]), "+f"(c[1]), "+f"(c[2]), "+f"(c[3])
        : "r"(a[0]), "r"(a[1]), "r"(a[2]), "r"(a[3]), "r"(b[0]), "r"(b[1]));
}
// split fp32 pair -> bf16x2 hi pair + lo pair (a = low b16, b = high b16)
__device__ __forceinline__ void split2(float xa, float xb, uint32_t& hp, uint32_t& lp) {
    asm("cvt.rn.bf16x2.f32 %0, %1, %2;" : "=r"(hp) : "f"(xb), "f"(xa));
    float ha = __uint_as_float(hp << 16);
    float hb = __uint_as_float(hp & 0xFFFF0000u);
    float la = xa - ha, lb = xb - hb;
    asm("cvt.rn.bf16x2.f32 %0, %1, %2;" : "=r"(lp) : "f"(lb), "f"(la));
}

// ---------------- twiddle init (+ bf16 synthesis tables) ----------------
__global__ void k_twiddle() {
    int idx = blockIdx.x * blockDim.x + threadIdx.x;   // 8192 threads
    if (idx < M2V * WW) {
        int ky = idx >> 8, w = idx & 255;
        int ph = (ky * w) & 255;
        float s, c;
        sincosf(-TWO_PI * (float)ph * (1.0f / 256.0f), &s, &c);
        g_TfwT[w * 16 + ky] = pk(c, s);
    }
    if (idx < 32 * HH) {
        int kxi = idx >> 8, h = idx & 255;
        int kx = (kxi < 16) ? kxi : (224 + kxi);
        int ph = (kx * h) & 255;
        float s, c;
        sincosf(-TWO_PI * (float)ph * (1.0f / 256.0f), &s, &c);
        g_Tfh[idx] = make_float2(c, s);
        g_Tih[idx] = make_float2(c, -s);
    }
    // synthesis table: [px][k], k<16: cos(2pi*k*px/256)/N^2 ; k>=16: sin(..)/N^2
    if (idx < 8192) {
        int px = idx >> 5, k = idx & 31;
        int ky = k & 15;
        int ph = (ky * px) & 255;
        float s, c;
        sincosf(TWO_PI * (float)ph * (1.0f / 256.0f), &s, &c);
        float val = ((k < 16) ? c : s) * (1.0f / 65536.0f);
        __nv_bfloat16 hi = __float2bfloat16_rn(val);
        __nv_bfloat16 lo = __float2bfloat16_rn(val - __bfloat162float(hi));
        uint32_t off = SW64((uint32_t)(px * 64 + k * 2));
        *(__nv_bfloat16*)(g_TsbH + off) = hi;
        *(__nv_bfloat16*)(g_TsbL + off) = lo;
    }
}

// ---------------- conv-weight bf16 prep: [l][och][ch] SW128, hi/lo ----------------
__global__ void k_wbprep(const float* __restrict__ pww) {
    int tid = blockIdx.x * 256 + threadIdx.x;          // < NLAY*4096
    int l = tid >> 12, r = tid & 4095;
    int och = r >> 6, ch = r & 63;
    float w = pww[l * 4096 + och * 64 + ch];
    __nv_bfloat16 hi = __float2bfloat16_rn(w);
    __nv_bfloat16 lo = __float2bfloat16_rn(w - __bfloat162float(hi));
    uint32_t off = SW128((uint32_t)(och * 128 + ch * 2));
    *(__nv_bfloat16*)(g_WbH + l * 8192 + off) = hi;
    *(__nv_bfloat16*)(g_WbL + l * 8192 + off) = lo;
}

// ---------------- spectral-weight transpose ----------------
__global__ void k_wt(const float* __restrict__ w1r, const float* __restrict__ w1i,
                     const float* __restrict__ w2r, const float* __restrict__ w2i) {
    int tid = blockIdx.x * blockDim.x + threadIdx.x;
    if (tid >= NLAY * 512 * WID * WID) return;
    int o   = tid & 63;
    int i   = (tid >> 6) & 63;
    int m   = (tid >> 12) & 511;
    int l   = tid >> 21;
    int kxi = m >> 4;
    int ky  = m & 15;
    int kk  = (kxi & 15) * 16 + ky;
    size_t src = ((size_t)(l * 64 + i) * 64 + o) * 256 + kk;
    float r, im;
    if (kxi < 16) { r = w1r[src]; im = w1i[src]; }
    else          { r = w2r[src]; im = w2i[src]; }
    g_Wt[tid] = make_float2(r, im);
}

// ---------------- fc0 lift ----------------
__global__ void __launch_bounds__(256) k_fc0(const float* __restrict__ x,
                                             const float* __restrict__ w,
                                             const float* __restrict__ bias) {
    __shared__ ull wp[CIN * 32];
    __shared__ ull bp[32];
    int t = threadIdx.x;
    for (int k = t; k < CIN * 32; k += 256) {
        int d2 = k & 31, c = k >> 5;
        wp[c * 32 + d2] = pk(w[(2 * d2) * CIN + c], w[(2 * d2 + 1) * CIN + c]);
    }
    if (t < 32) bp[t] = pk(bias[2 * t], bias[2 * t + 1]);
    __syncthreads();
    int p  = blockIdx.x * 256 + t;
    int b  = p >> 16;
    int sp = p & 65535;
    ull xx[CIN];
#pragma unroll
    for (int c = 0; c < CIN; c++) {
        float v = x[((size_t)(b * CIN + c) << 16) + sp];
        xx[c] = pk(v, v);
    }
#pragma unroll
    for (int d2 = 0; d2 < 32; d2++) {
        ull a = bp[d2];
#pragma unroll
        for (int c = 0; c < CIN; c++) a = ff2(xx[c], wp[c * 32 + d2], a);
        float2 f = upk(a);
        g_h0[((size_t)(b * WID + 2 * d2) << 16) + sp]     = f.x;
        g_h0[((size_t)(b * WID + 2 * d2 + 1) << 16) + sp] = f.y;
    }
}

// ---------------- forward DFT along w (R5) ----------------
__global__ void __launch_bounds__(256) k_dftw(const float* __restrict__ hin) {
    extern __shared__ char sm[];
    ull*   TshT = (ull*)sm;
    float* xsT  = (float*)(sm + 32768);
    int t = threadIdx.x;
    for (int k = t; k < 4096; k += 256) TshT[k] = g_TfwT[k];
    int kyh = t & 1;
    int rg  = t >> 1;
    size_t rbase = (size_t)blockIdx.x * 256;

    ull acc[2][8];
#pragma unroll
    for (int j = 0; j < 2; j++)
#pragma unroll
        for (int k = 0; k < 8; k++) acc[j][k] = 0ULL;

    for (int c = 0; c < 16; c++) {
        __syncthreads();
        for (int k = t; k < 4096; k += 256) {
            int wl = k & 15, row = k >> 4;
            xsT[wl * 258 + row] = hin[(rbase + row) * 256 + c * 16 + wl];
        }
        __syncthreads();
#pragma unroll
        for (int wl = 0; wl < 16; wl++) {
            float2 v = *(const float2*)&xsT[wl * 258 + rg * 2];
            ull v0 = pk(v.x, v.x), v1 = pk(v.y, v.y);
            const ulonglong2* tp =
                (const ulonglong2*)&TshT[(c * 16 + wl) * 16 + kyh * 8];
#pragma unroll
            for (int q = 0; q < 4; q++) {
                ulonglong2 tw = tp[q];
                acc[0][2 * q]     = ff2(v0, tw.x, acc[0][2 * q]);
                acc[0][2 * q + 1] = ff2(v0, tw.y, acc[0][2 * q + 1]);
                acc[1][2 * q]     = ff2(v1, tw.x, acc[1][2 * q]);
                acc[1][2 * q + 1] = ff2(v1, tw.y, acc[1][2 * q + 1]);
            }
        }
    }
    ull* outp = (ull*)g_Fw;
#pragma unroll
    for (int j = 0; j < 2; j++) {
        size_t r = rbase + rg * 2 + j;
        ulonglong2* op = (ulonglong2*)(outp + r * 16 + kyh * 8);
#pragma unroll
        for (int q = 0; q < 4; q++) {
            ulonglong2 st; st.x = acc[j][2 * q]; st.y = acc[j][2 * q + 1];
            op[q] = st;
        }
    }
}

// ---------------- forward DFT along h (R5) ----------------
__global__ void k_dfth() {
    extern __shared__ float2 sh[];
    float2* Fsh = sh;
    float2* Tsh = sh + 4096;
    int t = threadIdx.x;
    int bc = blockIdx.x;
    for (int k = t; k < 4096; k += 256) Fsh[k] = g_Fw[(size_t)bc * 4096 + k];
    for (int k = t; k < 8192; k += 256) Tsh[k] = g_Tfh[k];
    __syncthreads();
#pragma unroll
    for (int mm = 0; mm < 2; mm++) {
        int m = t + mm * 256;
        int kxi = m >> 4, ky = m & 15;
        float sr = 0.f, si = 0.f;
        for (int h = 0; h < 256; h++) {
            float2 f  = Fsh[h * 16 + ky];
            float2 tw = Tsh[kxi * 256 + h];
            sr = fmaf(f.x, tw.x, fmaf(-f.y, tw.y, sr));
            si = fmaf(f.x, tw.y, fmaf( f.y, tw.x, si));
        }
        g_Fm[(size_t)bc * 512 + m] = make_float2(sr, si);
    }
}

// ---------------- channel mixing (R5) ----------------
__global__ void k_mix(int layer) {
    __shared__ float2 Wm[WID * WID];
    __shared__ float2 Fsh[BB * WID];
    int t = threadIdx.x;
    int m = blockIdx.x;
    const float2* wsrc = g_Wt + ((size_t)layer * 512 + m) * 4096;
    for (int k = t; k < 4096; k += 256) Wm[k] = wsrc[k];
    for (int k = t; k < 1024; k += 256) {
        int b = k >> 6, i = k & 63;
        Fsh[k] = g_Fm[(size_t)(b * 64 + i) * 512 + m];
    }
    __syncthreads();
#pragma unroll
    for (int u = 0; u < 4; u++) {
        int outi = t + u * 256;
        int b = outi >> 6, o = outi & 63;
        float sr = 0.f, si = 0.f;
#pragma unroll 8
        for (int i = 0; i < 64; i++) {
            float2 f = Fsh[b * 64 + i];
            float2 w = Wm[i * 64 + o];
            sr = fmaf(f.x, w.x, fmaf(-f.y, w.y, sr));
            si = fmaf(f.x, w.y, fmaf( f.y, w.x, si));
        }
        g_Gm[(size_t)(b * 64 + o) * 512 + m] = make_float2(sr, si);
    }
}

// ---------------- inverse transform along h (R5) ----------------
__global__ void k_idfth() {
    extern __shared__ char shb[];
    ulonglong2* Gsh2 = (ulonglong2*)shb;
    float2*     Tsh  = (float2*)(shb + 8192);
    int t = threadIdx.x;
    int bc = blockIdx.x;
    for (int k = t; k < 512; k += 256) {
        float2 g = g_Gm[(size_t)bc * 512 + k];
        ulonglong2 d; d.x = pk(g.x, g.x); d.y = pk(g.y, g.y);
        Gsh2[k] = d;
    }
    for (int k = t; k < 8192; k += 256) Tsh[k] = g_Tih[k];
    __syncthreads();
    int h = t;
    ull acc[16];
#pragma unroll
    for (int k = 0; k < 16; k++) acc[k] = 0ULL;
    for (int kxi = 0; kxi < 32; kxi++) {
        float2 tw = Tsh[kxi * 256 + h];
        ull t1 = pk(tw.x, tw.y);
        ull t2 = pk(-tw.y, tw.x);
        const ulonglong2* gp = &Gsh2[kxi * 16];
#pragma unroll
        for (int ky = 0; ky < 16; ky++) {
            ulonglong2 g = gp[ky];
            acc[ky] = ff2(g.x, t1, acc[ky]);
            acc[ky] = ff2(g.y, t2, acc[ky]);
        }
    }
    ull* outp = (ull*)(g_Gw + ((size_t)bc * 256 + h) * 16);
#pragma unroll
    for (int ky = 0; ky < 16; ky++) outp[ky] = acc[ky];
}

// ============ k_fused_mma: HMMA conv + synthesis-as-GEMM + bias + gelu ============
// grid 4096 = (b,row), 256 threads = 8 warps, warp w -> px w*32..w*32+31.
// acc[256px x 64och] = Xsplit·W^T (K=64, 3 products) + Tsplit·Gd^T (K=32, 3 products)
// dyn smem layout (bytes):
//  0      XH [256px][64ch] bf16 SW128   32768
//  32768  XL                            32768
//  65536  WH [64och][64ch] SW128         8192
//  73728  WL                             8192
//  81920  TH [256px][32k]  SW64         16384
//  98304  TL                            16384
//  114688 GH [64och][32k]  SW64          4096
//  118784 GL                             4096
//  122880 bias[64]                        256   -> total 123136
//  stage (post-mma) overlaps [0, 66560)
__global__ void __launch_bounds__(256)
k_fused_mma(const float* __restrict__ hin, float* __restrict__ hout,
            int layer, const float* __restrict__ pwb, int dogelu) {
    extern __shared__ char smx[];
    const uint32_t sb = smem_u32(smx);
    int t = threadIdx.x;
    int b = blockIdx.x >> 8, row = blockIdx.x & 255;

    // ---- stage X (activations) as bf16 hi/lo, SW128 ----
    {
        const float* xp = hin + ((size_t)(b * 64) << 16) + row * 256 + t;
#pragma unroll
        for (int i2 = 0; i2 < 32; i2++) {
            float xa = xp[(size_t)(2 * i2) << 16];
            float xb = xp[(size_t)(2 * i2 + 1) << 16];
            uint32_t hp, lp;
            split2(xa, xb, hp, lp);
            uint32_t off = SW128((uint32_t)(t * 128 + i2 * 4));
            *(uint32_t*)(smx + off)         = hp;
            *(uint32_t*)(smx + 32768 + off) = lp;
        }
    }
    // ---- copy prepped W tiles (linear, already swizzled) ----
    {
        const ulonglong2* srcH = (const ulonglong2*)(g_WbH + layer * 8192);
        const ulonglong2* srcL = (const ulonglong2*)(g_WbL + layer * 8192);
        ulonglong2* dstH = (ulonglong2*)(smx + 65536);
        ulonglong2* dstL = (ulonglong2*)(smx + 73728);
        for (int k = t; k < 512; k += 256) { dstH[k] = srcH[k]; dstL[k] = srcL[k]; }
    }
    // ---- copy prepped synthesis T tiles ----
    {
        const ulonglong2* srcH = (const ulonglong2*)g_TsbH;
        const ulonglong2* srcL = (const ulonglong2*)g_TsbL;
        ulonglong2* dstH = (ulonglong2*)(smx + 81920);
        ulonglong2* dstL = (ulonglong2*)(smx + 98304);
        for (int k = t; k < 1024; k += 256) { dstH[k] = srcH[k]; dstL[k] = srcL[k]; }
    }
    // ---- stage Gd as bf16 hi/lo, SW64: row och, k<16: 2gx (ky0: gx); k>=16: -2gy (ky0: 0)
    for (int k = t; k < 1024; k += 256) {
        int och = k >> 4, ky = k & 15;
        float2 g = g_Gw[(((size_t)(b * 64 + och)) * 256 + row) * 16 + ky];
        float vx = (ky == 0) ? g.x : 2.0f * g.x;
        float vy = (ky == 0) ? 0.0f : -2.0f * g.y;
        __nv_bfloat16 hx = __float2bfloat16_rn(vx);
        __nv_bfloat16 lx = __float2bfloat16_rn(vx - __bfloat162float(hx));
        __nv_bfloat16 hy = __float2bfloat16_rn(vy);
        __nv_bfloat16 ly = __float2bfloat16_rn(vy - __bfloat162float(hy));
        uint32_t off1 = SW64((uint32_t)(och * 64 + ky * 2));
        uint32_t off2 = SW64((uint32_t)(och * 64 + (16 + ky) * 2));
        *(__nv_bfloat16*)(smx + 114688 + off1) = hx;
        *(__nv_bfloat16*)(smx + 118784 + off1) = lx;
        *(__nv_bfloat16*)(smx + 114688 + off2) = hy;
        *(__nv_bfloat16*)(smx + 118784 + off2) = ly;
    }
    if (t < 64) ((float*)(smx + 122880))[t] = pwb[t];
    __syncthreads();

    // ---- MMA mainloop ----
    const int lane = t & 31;
    const int wrp  = t >> 5;
    const int pxb  = wrp * 32;
    const int grp = lane >> 3, rr = lane & 7;
    const int a_m = ((grp & 1) << 3) + rr;   // + mt*16
    const int a_k = (grp >> 1) << 3;
    const int b_n = ((grp >> 1) << 3) + rr;
    const int b_k = (grp & 1) << 3;

    float acc[2][8][4];
#pragma unroll
    for (int mt = 0; mt < 2; mt++)
#pragma unroll
        for (int n8 = 0; n8 < 8; n8++)
#pragma unroll
            for (int c = 0; c < 4; c++) acc[mt][n8][c] = 0.0f;

    // conv: K=64, SW128 tiles (X rows 128B, W rows 128B)
#pragma unroll
    for (int kt = 0; kt < 4; kt++) {
        int kb = kt * 16;
        uint32_t ah[2][4], al[2][4];
#pragma unroll
        for (int mt = 0; mt < 2; mt++) {
            uint32_t aoff = SW128((uint32_t)((pxb + mt * 16 + a_m) * 128 + (kb + a_k) * 2));
            ldsm4(ah[mt][0], ah[mt][1], ah[mt][2], ah[mt][3], sb + aoff);
            ldsm4(al[mt][0], al[mt][1], al[mt][2], al[mt][3], sb + 32768 + aoff);
        }
#pragma unroll
        for (int jp = 0; jp < 4; jp++) {
            int nb = jp * 16;
            uint32_t bh[4], bl[4];
            uint32_t boff = SW128((uint32_t)((nb + b_n) * 128 + (kb + b_k) * 2));
            ldsm4(bh[0], bh[1], bh[2], bh[3], sb + 65536 + boff);
            ldsm4(bl[0], bl[1], bl[2], bl[3], sb + 73728 + boff);
#pragma unroll
            for (int mt = 0; mt < 2; mt++) {
#pragma unroll
                for (int ntl = 0; ntl < 2; ntl++) {
                    float* c = acc[mt][jp * 2 + ntl];
                    mma16816(c, ah[mt], &bh[ntl * 2]);
                    mma16816(c, ah[mt], &bl[ntl * 2]);
                    mma16816(c, al[mt], &bh[ntl * 2]);
                }
            }
        }
    }
    // synthesis: K=32, SW64 tiles (T rows 64B, Gd rows 64B)
#pragma unroll
    for (int kt = 0; kt < 2; kt++) {
        int kb = kt * 16;
        uint32_t ah[2][4], al[2][4];
#pragma unroll
        for (int mt = 0; mt < 2; mt++) {
            uint32_t aoff = SW64((uint32_t)((pxb + mt * 16 + a_m) * 64 + (kb + a_k) * 2));
            ldsm4(ah[mt][0], ah[mt][1], ah[mt][2], ah[mt][3], sb + 81920 + aoff);
            ldsm4(al[mt][0], al[mt][1], al[mt][2], al[mt][3], sb + 98304 + aoff);
        }
#pragma unroll
        for (int jp = 0; jp < 4; jp++) {
            int nb = jp * 16;
            uint32_t bh[4], bl[4];
            uint32_t boff = SW64((uint32_t)((nb + b_n) * 64 + (kb + b_k) * 2));
            ldsm4(bh[0], bh[1], bh[2], bh[3], sb + 114688 + boff);
            ldsm4(bl[0], bl[1], bl[2], bl[3], sb + 118784 + boff);
#pragma unroll
            for (int mt = 0; mt < 2; mt++) {
#pragma unroll
                for (int ntl = 0; ntl < 2; ntl++) {
                    float* c = acc[mt][jp * 2 + ntl];
                    mma16816(c, ah[mt], &bh[ntl * 2]);
                    mma16816(c, ah[mt], &bl[ntl * 2]);
                    mma16816(c, al[mt], &bh[ntl * 2]);
                }
            }
        }
    }

    // ---- epilogue: bias + gelu -> stage [och][260] -> coalesced store ----
    __syncthreads();   // all warps done reading smem before stage overwrite
    {
        float* stage = (float*)smx;           // [64][260] floats, 66560 B
        const float* bsh = (const float*)(smx + 122880);
        int g = lane >> 2, tq = lane & 3;
#pragma unroll
        for (int mt = 0; mt < 2; mt++) {
            int px0 = pxb + mt * 16 + g;
#pragma unroll
            for (int n8 = 0; n8 < 8; n8++) {
                int och = n8 * 8 + tq * 2;
                float b0 = bsh[och], b1 = bsh[och + 1];
                float v00 = acc[mt][n8][0] + b0;
                float v01 = acc[mt][n8][1] + b1;
                float v10 = acc[mt][n8][2] + b0;
                float v11 = acc[mt][n8][3] + b1;
                if (dogelu) {
                    v00 = gelu_fast(v00); v01 = gelu_fast(v01);
                    v10 = gelu_fast(v10); v11 = gelu_fast(v11);
                }
                stage[och * 260 + px0]           = v00;
                stage[(och + 1) * 260 + px0]     = v01;
                stage[och * 260 + px0 + 8]       = v10;
                stage[(och + 1) * 260 + px0 + 8] = v11;
            }
        }
    }
    __syncthreads();
    {
        const float* stage = (const float*)smx;
        float* outp = hout + ((size_t)(b * 64) << 16) + row * 256 + t;
#pragma unroll 8
        for (int i = 0; i < 64; i++)
            outp[(size_t)i << 16] = stage[i * 260 + t];
    }
}

// ---------------- fused projection (R5, f32x2) ----------------
__global__ void __launch_bounds__(256, 2)
k_final(const float* __restrict__ hin, float* __restrict__ out,
        const float* __restrict__ w1, const float* __restrict__ b1,
        const float* __restrict__ w2, const float* __restrict__ b2) {
    __shared__ ull w1p[FCH * 32];
    __shared__ ull w2t[FCH * 10];
    __shared__ float b1sh[FCH];
    __shared__ ull b2p[10];
    int t = threadIdx.x;
    for (int k = t; k < FCH * 32; k += 256) w1p[k] = ((const ull*)w1)[k];
    for (int k = t; k < FCH * 10; k += 256) {
        int o2 = k >> 7, j = k & 127;
        w2t[j * 10 + o2] = pk(w2[(2 * o2) * FCH + j], w2[(2 * o2 + 1) * FCH + j]);
    }
    if (t < FCH) b1sh[t] = b1[t];
    if (t < 10)  b2p[t] = pk(b2[2 * t], b2[2 * t + 1]);
    __syncthreads();

    int b   = blockIdx.x >> 8;
    int row = blockIdx.x & 255;
    size_t sp = ((size_t)row << 8) + t;
    size_t base = ((size_t)(b * WID) << 16) + sp;
    ull xv[32];
#pragma unroll
    for (int i2 = 0; i2 < 32; i2++)
        xv[i2] = pk(hin[base + ((size_t)(2 * i2) << 16)],
                    hin[base + ((size_t)(2 * i2 + 1) << 16)]);
    ull acc[10];
#pragma unroll
    for (int o2 = 0; o2 < 10; o2++) acc[o2] = b2p[o2];

    for (int j = 0; j < FCH; j++) {
        const ulonglong2* wp = (const ulonglong2*)&w1p[j * 32];
        ull h2 = 0ULL;
#pragma unroll
        for (int k = 0; k < 16; k++) {
            ulonglong2 u = wp[k];
            h2 = ff2(xv[2 * k], u.x, h2);
            h2 = ff2(xv[2 * k + 1], u.y, h2);
        }
        float2 hf = upk(h2);
        float hv = gelu_fast(hf.x + hf.y + b1sh[j]);
        ull hh = pk(hv, hv);
        const ulonglong2* w2p = (const ulonglong2*)&w2t[j * 10];
#pragma unroll
        for (int k = 0; k < 5; k++) {
            ulonglong2 u = w2p[k];
            acc[2 * k]     = ff2(hh, u.x, acc[2 * k]);
            acc[2 * k + 1] = ff2(hh, u.y, acc[2 * k + 1]);
        }
    }
#pragma unroll
    for (int o2 = 0; o2 < 10; o2++) {
        float2 a = upk(acc[o2]);
        out[((size_t)(b * CO + 2 * o2) << 16) + sp]     = a.x;
        out[((size_t)(b * CO + 2 * o2 + 1) << 16) + sp] = a.y;
    }
}

// ---------------- orchestration ----------------
extern "C" void kernel_launch(void* const* d_in, const int* in_sizes, int n_in,
                              void* d_out, int out_size) {
    const float* x    = (const float*)d_in[0];
    const float* w1r  = (const float*)d_in[1];
    const float* w1i  = (const float*)d_in[2];
    const float* w2r  = (const float*)d_in[3];
    const float* w2i  = (const float*)d_in[4];
    const float* pww  = (const float*)d_in[5];
    const float* pwb  = (const float*)d_in[6];
    const float* fc0w = (const float*)d_in[7];
    const float* fc0b = (const float*)d_in[8];
    const float* fc1w = (const float*)d_in[9];
    const float* fc1b = (const float*)d_in[10];
    const float* fc2w = (const float*)d_in[11];
    const float* fc2b = (const float*)d_in[12];
    float* out = (float*)d_out;

    cudaFuncSetAttribute(k_dftw,      cudaFuncAttributeMaxDynamicSharedMemorySize, 49280);
    cudaFuncSetAttribute(k_dfth,      cudaFuncAttributeMaxDynamicSharedMemorySize, 98304);
    cudaFuncSetAttribute(k_idfth,     cudaFuncAttributeMaxDynamicSharedMemorySize, 73728);
    cudaFuncSetAttribute(k_fused_mma, cudaFuncAttributeMaxDynamicSharedMemorySize, 123136);

    void *p0, *p1;
    cudaGetSymbolAddress(&p0, g_h0);
    cudaGetSymbolAddress(&p1, g_h1);
    float* hb[2] = {(float*)p0, (float*)p1};

    k_twiddle<<<32, 256>>>();
    k_wbprep<<<NLAY * 4096 / 256, 256>>>(pww);
    k_wt<<<(NLAY * 512 * WID * WID) / 256, 256>>>(w1r, w1i, w2r, w2i);
    k_fc0<<<NPIX / 256, 256>>>(x, fc0w, fc0b);

    for (int l = 0; l < NLAY; l++) {
        const float* hi = hb[l & 1];
        float*       ho = hb[(l + 1) & 1];
        k_dftw<<<1024, 256, 49280>>>(hi);
        k_dfth<<<1024, 256, 98304>>>();
        k_mix<<<512, 256>>>(l);
        k_idfth<<<1024, 256, 73728>>>();
        k_fused_mma<<<4096, 256, 123136>>>(hi, ho, l, pwb + (size_t)l * WID,
                                           (l < NLAY - 1) ? 1 : 0);
    }
    k_final<<<4096, 256>>>(hb[0], out, fc1w, fc1b, fc2w, fc2b);
}